// round 3
// baseline (speedup 1.0000x reference)
#include <cuda_runtime.h>

// Problem constants (fixed by the dataset)
#define Bc   8
#define Nc   6
#define Mc   64
#define Vc   32000
#define Tc   8
#define NP1  7            // N+1 template span dim
#define NV4  (Vc/4)       // 8000 float4 per row
#define CH   4            // V chunks per (b,m)
#define CHUNK (NV4/CH)    // 2000 float4 per chunk
#define THR  256

// Tiny scratch (device globals — no allocation allowed).
// g_any is written unconditionally by every chunk each run -> no init needed.
__device__ int g_any[Bc * Tc * Mc * CH];  // 1 if chunk saw out_v > out0 for (b,t,m,c)
__device__ int g_srct[Bc * Mc];           // source t for output row (b,m), -1 = zero row
__device__ int g_srcm[Bc * Mc];           // source m within that t-step

// ---------------------------------------------------------------------------
// Kernel 1: per (b,m,chunk) stream dec once; write out_0 to d_out; per t flag
// whether any out_v > out0 in this chunk. Weights + out0 live in SHARED
// (block-uniform -> broadcast LDS) to keep regs low; loads double-buffered.
// ---------------------------------------------------------------------------
template <int S>
__device__ __forceinline__ void amax_body(
    const float* __restrict__ dec,
    const float (*__restrict__ w)[NP1],   // shared masked template [T][NP1]
    const float* __restrict__ out0,       // shared out0 per t [T]
    int* smask,
    int b, int m, int c, int tid,
    float* __restrict__ out)
{
    constexpr int SS = (S > 0) ? S : 1;

    const float4* dp[SS];
#pragma unroll
    for (int s = 0; s < S; ++s)
        dp[s] = (const float4*)(dec + ((b * Nc + s) * Mc + m) * Vc);
    float4* o = (float4*)(out + (b * Mc + m) * Vc);

    const int base = c * CHUNK;
    unsigned mask = 0;

    // double-buffered stream over the chunk
    float4 cur[SS];
    int i = tid;
    if (i < CHUNK) {
#pragma unroll
        for (int s = 0; s < S; ++s) cur[s] = dp[s][base + i];
    }
    for (; i < CHUNK; i += THR) {
        int ni = i + THR;
        float4 nxt[SS];
        if (ni < CHUNK) {
#pragma unroll
            for (int s = 0; s < S; ++s) nxt[s] = dp[s][base + ni];  // prefetch
        }

        int gi = base + i;
#pragma unroll
        for (int t = 0; t < Tc; ++t) {
            float ax = 0.f, ay = 0.f, az = 0.f, aw = 0.f;
#pragma unroll
            for (int s = 0; s < S; ++s) {
                float wv = w[t][s + 1];            // broadcast LDS
                ax = fmaf(wv, cur[s].x, ax);
                ay = fmaf(wv, cur[s].y, ay);
                az = fmaf(wv, cur[s].z, az);
                aw = fmaf(wv, cur[s].w, aw);
            }
            if (m == 0 && gi == 0) ax += w[t][0];  // pad one-hot (chunk 0 only)
            if (t == 0) {                           // store out_0 speculatively
                float4 r; r.x = ax; r.y = ay; r.z = az; r.w = aw;
                o[gi] = r;
            }
            float m1 = fmaxf(fmaxf(ax, ay), fmaxf(az, aw));
            mask |= (m1 > out0[t]) ? (1u << t) : 0u;
        }

        if (ni < CHUNK) {
#pragma unroll
            for (int s = 0; s < S; ++s) cur[s] = nxt[s];
        }
    }

    unsigned wm = __reduce_or_sync(0xffffffffu, mask);
    if ((tid & 31) == 0) atomicOr(smask, (int)wm);
    __syncthreads();
    if (tid < Tc)
        g_any[((b * Tc + tid) * Mc + m) * CH + c] = (*smask >> tid) & 1;
}

__global__ __launch_bounds__(THR, 3) void k_amax(
    const float* __restrict__ dec,
    const float* __restrict__ tmpl,
    const int*   __restrict__ spans,
    float*       __restrict__ out)
{
    int bid = blockIdx.x;
    int c = bid & (CH - 1);
    int m = (bid >> 2) & (Mc - 1);
    int b = bid >> 8;
    int tid = threadIdx.x;

    __shared__ float w[Tc][NP1];
    __shared__ float out0[Tc];
    __shared__ int smask;
    if (tid == 0) smask = 0;

    int S = spans[b];   // 0..5, uniform per block
    if (tid < Tc * NP1) {
        int t = tid / NP1, s = tid % NP1;
        w[t][s] = (s <= S) ? tmpl[(b * Tc + t) * NP1 + s] : 0.f;
    }
    __syncthreads();

    // out0[t] — computed with the SAME fmaf chain as the main loop so the
    // v=0 element in chunk 0 compares exactly equal (no false "greater").
    if (tid < Tc) {
        int t = tid;
        float a = 0.f;
        for (int s = 0; s < S; ++s)
            a = fmaf(w[t][s + 1], dec[((b * Nc + s) * Mc + m) * Vc], a);
        if (m == 0) a += w[t][0];
        out0[t] = a;
    }
    __syncthreads();

    switch (S) {
        case 0: amax_body<0>(dec, w, out0, &smask, b, m, c, tid, out); break;
        case 1: amax_body<1>(dec, w, out0, &smask, b, m, c, tid, out); break;
        case 2: amax_body<2>(dec, w, out0, &smask, b, m, c, tid, out); break;
        case 3: amax_body<3>(dec, w, out0, &smask, b, m, c, tid, out); break;
        case 4: amax_body<4>(dec, w, out0, &smask, b, m, c, tid, out); break;
        default: amax_body<5>(dec, w, out0, &smask, b, m, c, tid, out); break;
    }
}

// ---------------------------------------------------------------------------
// Kernel 2: sequential T-step scan per batch -> (src_t, src_m) map per row.
// ---------------------------------------------------------------------------
__global__ void k_scan()
{
    int b = blockIdx.x;
    int tid = threadIdx.x;              // 64 threads = M
    __shared__ int s_idx, s_len;
    __shared__ int row[Mc];

    int srct = -1, srcm = 0;
    if (tid == 0) s_idx = 0;
    __syncthreads();

    for (int t = 0; t < Tc; ++t) {
        const int* p = &g_any[((b * Tc + t) * Mc + tid) * CH];
        row[tid] = (p[0] | p[1] | p[2] | p[3]) ? 0 : 1;   // iszero flag
        __syncthreads();
        if (tid == 0) {
            int len = Mc;
            for (int mm = 0; mm < Mc; ++mm)
                if (row[mm]) { len = mm; break; }
            int rem = Mc - s_idx;
            if (len > rem) len = rem;
            s_len = len;
        }
        __syncthreads();
        int idx = s_idx, len = s_len;
        if (tid >= idx && tid < idx + len) { srct = t; srcm = tid - idx; }
        __syncthreads();
        if (tid == 0) s_idx = idx + len;
        __syncthreads();
    }
    g_srct[b * Mc + tid] = srct;
    g_srcm[b * Mc + tid] = srcm;
}

// ---------------------------------------------------------------------------
// Kernel 3: fixup — only rows whose map differs from (t=0, m) need work.
// ---------------------------------------------------------------------------
template <int S>
__device__ __forceinline__ void row_body(
    const float* __restrict__ dec,
    const float* __restrict__ tmpl,
    int b, int st, int sm, float4* __restrict__ o, int tid)
{
    constexpr int SS = (S > 0) ? S : 1;
    float wl[SS];
    float wt0 = tmpl[(b * Tc + st) * NP1];
#pragma unroll
    for (int s = 0; s < S; ++s) wl[s] = tmpl[(b * Tc + st) * NP1 + s + 1];

    const float4* dp[SS];
#pragma unroll
    for (int s = 0; s < S; ++s)
        dp[s] = (const float4*)(dec + ((b * Nc + s) * Mc + sm) * Vc);

    for (int i = tid; i < NV4; i += THR) {
        float ax = 0.f, ay = 0.f, az = 0.f, aw = 0.f;
#pragma unroll
        for (int s = 0; s < S; ++s) {
            float4 d = dp[s][i];
            ax = fmaf(wl[s], d.x, ax);
            ay = fmaf(wl[s], d.y, ay);
            az = fmaf(wl[s], d.z, az);
            aw = fmaf(wl[s], d.w, aw);
        }
        if (sm == 0 && i == 0) ax += wt0;   // pad one-hot
        float4 r; r.x = ax; r.y = ay; r.z = az; r.w = aw;
        o[i] = r;
    }
}

__global__ __launch_bounds__(THR) void k_fix(
    const float* __restrict__ dec,
    const float* __restrict__ tmpl,
    const int*   __restrict__ spans,
    float*       __restrict__ out)
{
    int b = blockIdx.x >> 6;
    int m = blockIdx.x & 63;
    int tid = threadIdx.x;

    int st = g_srct[b * Mc + m];
    int sm = g_srcm[b * Mc + m];
    if (st == 0 && sm == m) return;     // common case: out_0 already in place

    float4* o = (float4*)(out + (b * Mc + m) * Vc);
    if (st < 0) {
        float4 z; z.x = z.y = z.z = z.w = 0.f;
        for (int i = tid; i < NV4; i += THR) o[i] = z;
        return;
    }
    switch (spans[b]) {
        case 0: row_body<0>(dec, tmpl, b, st, sm, o, tid); break;
        case 1: row_body<1>(dec, tmpl, b, st, sm, o, tid); break;
        case 2: row_body<2>(dec, tmpl, b, st, sm, o, tid); break;
        case 3: row_body<3>(dec, tmpl, b, st, sm, o, tid); break;
        case 4: row_body<4>(dec, tmpl, b, st, sm, o, tid); break;
        default: row_body<5>(dec, tmpl, b, st, sm, o, tid); break;
    }
}

// ---------------------------------------------------------------------------
extern "C" void kernel_launch(void* const* d_in, const int* in_sizes, int n_in,
                              void* d_out, int out_size)
{
    const float* dec   = (const float*)d_in[0];   // [B,N,M,V] fp32
    const float* tmpl  = (const float*)d_in[1];   // [B,T,N+1] fp32
    const int*   spans = (const int*)d_in[2];     // [B] int32
    float*       out   = (float*)d_out;           // [B,M,V] fp32

    k_amax<<<Bc * Mc * CH, THR>>>(dec, tmpl, spans, out);
    k_scan<<<Bc, Mc>>>();
    k_fix <<<Bc * Mc, THR>>>(dec, tmpl, spans, out);
}

// round 4
// speedup vs baseline: 1.3708x; 1.3708x over previous
#include <cuda_runtime.h>

// Problem constants (fixed by the dataset)
#define Bc   8
#define Nc   6
#define Mc   64
#define Vc   32000
#define Tc   8
#define NP1  7            // N+1 template span dim
#define NV4  (Vc/4)       // 8000 float4 per row
#define CH   4            // V chunks per (b,m)
#define CHUNK (NV4/CH)    // 2000 float4 per chunk
#define THR  256

// Tiny scratch (device globals — no allocation allowed).
// g_any is written unconditionally by every chunk each run -> no init needed.
__device__ int g_any[Bc * Tc * Mc * CH];  // 1 if chunk saw out_v > out0 for (b,t,m,c)
__device__ int g_srct[Bc * Mc];           // source t for output row (b,m), -1 = zero row
__device__ int g_srcm[Bc * Mc];           // source m within that t-step

// ---------------------------------------------------------------------------
// Kernel 1: per (b,m,chunk) stream dec once; write out_0 to d_out; per t flag
// whether any out_v > out0 in this chunk. Weights in REGISTERS (R2 layout),
// loads batched 2-deep for MLP.
// ---------------------------------------------------------------------------
template <int S>
__device__ __forceinline__ void amax_body(
    const float* __restrict__ dec,
    const float (*__restrict__ w)[NP1],   // shared masked template [T][NP1]
    int* smask,
    int b, int m, int c, int tid,
    float* __restrict__ out)
{
    constexpr int SS = (S > 0) ? S : 1;
    float wl[Tc][SS];
    float w0[Tc];
#pragma unroll
    for (int t = 0; t < Tc; ++t) {
        w0[t] = w[t][0];
#pragma unroll
        for (int s = 0; s < S; ++s) wl[t][s] = w[t][s + 1];
    }

    // out0[t] — same fmaf chain as the main loop so the v=0 element in chunk 0
    // compares exactly equal (never strictly greater).
    float d0[SS];
#pragma unroll
    for (int s = 0; s < S; ++s) d0[s] = dec[((b * Nc + s) * Mc + m) * Vc];
    float out0[Tc];
#pragma unroll
    for (int t = 0; t < Tc; ++t) {
        float a = 0.f;
#pragma unroll
        for (int s = 0; s < S; ++s) a = fmaf(wl[t][s], d0[s], a);
        if (m == 0) a += w0[t];
        out0[t] = a;
    }

    const float4* dp[SS];
#pragma unroll
    for (int s = 0; s < S; ++s)
        dp[s] = (const float4*)(dec + ((b * Nc + s) * Mc + m) * Vc);
    float4* o = (float4*)(out + (b * Mc + m) * Vc);

    const int base = c * CHUNK;
    unsigned mask = 0;

    int i = tid;
    // main loop: 2 elements per trip, 2*S loads front-batched
    for (; i + THR < CHUNK; i += 2 * THR) {
        int g0 = base + i;
        int g1 = g0 + THR;
        float4 da[SS], db[SS];
#pragma unroll
        for (int s = 0; s < S; ++s) da[s] = dp[s][g0];
#pragma unroll
        for (int s = 0; s < S; ++s) db[s] = dp[s][g1];

#pragma unroll
        for (int t = 0; t < Tc; ++t) {
            float ax = 0.f, ay = 0.f, az = 0.f, aw = 0.f;
            float bx = 0.f, by = 0.f, bz = 0.f, bw = 0.f;
#pragma unroll
            for (int s = 0; s < S; ++s) {
                ax = fmaf(wl[t][s], da[s].x, ax);
                ay = fmaf(wl[t][s], da[s].y, ay);
                az = fmaf(wl[t][s], da[s].z, az);
                aw = fmaf(wl[t][s], da[s].w, aw);
                bx = fmaf(wl[t][s], db[s].x, bx);
                by = fmaf(wl[t][s], db[s].y, by);
                bz = fmaf(wl[t][s], db[s].z, bz);
                bw = fmaf(wl[t][s], db[s].w, bw);
            }
            if (m == 0 && g0 == 0) ax += w0[t];   // pad one-hot (chunk 0 only)
            if (t == 0) {
                float4 r; r.x = ax; r.y = ay; r.z = az; r.w = aw;
                o[g0] = r;
                float4 q; q.x = bx; q.y = by; q.z = bz; q.w = bw;
                o[g1] = q;
            }
            float m1 = fmaxf(fmaxf(fmaxf(ax, ay), fmaxf(az, aw)),
                             fmaxf(fmaxf(bx, by), fmaxf(bz, bw)));
            mask |= (m1 > out0[t]) ? (1u << t) : 0u;
        }
    }
    // tail: at most one element left
    if (i < CHUNK) {
        int gi = base + i;
        float4 da[SS];
#pragma unroll
        for (int s = 0; s < S; ++s) da[s] = dp[s][gi];
#pragma unroll
        for (int t = 0; t < Tc; ++t) {
            float ax = 0.f, ay = 0.f, az = 0.f, aw = 0.f;
#pragma unroll
            for (int s = 0; s < S; ++s) {
                ax = fmaf(wl[t][s], da[s].x, ax);
                ay = fmaf(wl[t][s], da[s].y, ay);
                az = fmaf(wl[t][s], da[s].z, az);
                aw = fmaf(wl[t][s], da[s].w, aw);
            }
            if (m == 0 && gi == 0) ax += w0[t];
            if (t == 0) {
                float4 r; r.x = ax; r.y = ay; r.z = az; r.w = aw;
                o[gi] = r;
            }
            float m1 = fmaxf(fmaxf(ax, ay), fmaxf(az, aw));
            mask |= (m1 > out0[t]) ? (1u << t) : 0u;
        }
    }

    unsigned wm = __reduce_or_sync(0xffffffffu, mask);
    if ((tid & 31) == 0) atomicOr(smask, (int)wm);
    __syncthreads();
    if (tid < Tc)
        g_any[((b * Tc + tid) * Mc + m) * CH + c] = (*smask >> tid) & 1;
}

__global__ __launch_bounds__(THR, 2) void k_amax(
    const float* __restrict__ dec,
    const float* __restrict__ tmpl,
    const int*   __restrict__ spans,
    float*       __restrict__ out)
{
    int bid = blockIdx.x;
    int c = bid & (CH - 1);
    int m = (bid >> 2) & (Mc - 1);
    int b = bid >> 8;
    int tid = threadIdx.x;

    __shared__ float w[Tc][NP1];
    __shared__ int smask;
    if (tid == 0) smask = 0;

    int S = spans[b];   // 0..5, uniform per block
    if (tid < Tc * NP1) {
        int t = tid / NP1, s = tid % NP1;
        w[t][s] = (s <= S) ? tmpl[(b * Tc + t) * NP1 + s] : 0.f;
    }
    __syncthreads();

    switch (S) {
        case 0: amax_body<0>(dec, w, &smask, b, m, c, tid, out); break;
        case 1: amax_body<1>(dec, w, &smask, b, m, c, tid, out); break;
        case 2: amax_body<2>(dec, w, &smask, b, m, c, tid, out); break;
        case 3: amax_body<3>(dec, w, &smask, b, m, c, tid, out); break;
        case 4: amax_body<4>(dec, w, &smask, b, m, c, tid, out); break;
        default: amax_body<5>(dec, w, &smask, b, m, c, tid, out); break;
    }
}

// ---------------------------------------------------------------------------
// Kernel 2: single-warp ballot scan per batch -> (src_t, src_m) per row.
// Lane L handles rows m=L and m=L+32.
// ---------------------------------------------------------------------------
__global__ void k_scan()
{
    int b = blockIdx.x;
    int lane = threadIdx.x;             // 32 threads

    int srct0 = -1, srcm0 = 0;          // row m = lane
    int srct1 = -1, srcm1 = 0;          // row m = lane + 32
    int idx = 0;                        // uniform across warp

    for (int t = 0; t < Tc; ++t) {
        const int* p0 = &g_any[((b * Tc + t) * Mc + lane) * CH];
        const int* p1 = &g_any[((b * Tc + t) * Mc + lane + 32) * CH];
        int nz0 = (p0[0] | p0[1] | p0[2] | p0[3]);   // argmax != 0
        int nz1 = (p1[0] | p1[1] | p1[2] | p1[3]);
        unsigned z0 = __ballot_sync(0xffffffffu, !nz0);  // iszero bits m=0..31
        unsigned z1 = __ballot_sync(0xffffffffu, !nz1);  // iszero bits m=32..63
        int len;
        if (z0) len = __ffs(z0) - 1;
        else if (z1) len = 32 + __ffs(z1) - 1;
        else len = Mc;
        int rem = Mc - idx;
        if (len > rem) len = rem;
        int m0 = lane, m1 = lane + 32;
        if (m0 >= idx && m0 < idx + len) { srct0 = t; srcm0 = m0 - idx; }
        if (m1 >= idx && m1 < idx + len) { srct1 = t; srcm1 = m1 - idx; }
        idx += len;
    }
    g_srct[b * Mc + lane] = srct0;
    g_srcm[b * Mc + lane] = srcm0;
    g_srct[b * Mc + lane + 32] = srct1;
    g_srcm[b * Mc + lane + 32] = srcm1;
}

// ---------------------------------------------------------------------------
// Kernel 3: fixup — only rows whose map differs from (t=0, m) need work.
// ---------------------------------------------------------------------------
template <int S>
__device__ __forceinline__ void row_body(
    const float* __restrict__ dec,
    const float* __restrict__ tmpl,
    int b, int st, int sm, float4* __restrict__ o, int tid)
{
    constexpr int SS = (S > 0) ? S : 1;
    float wl[SS];
    float wt0 = tmpl[(b * Tc + st) * NP1];
#pragma unroll
    for (int s = 0; s < S; ++s) wl[s] = tmpl[(b * Tc + st) * NP1 + s + 1];

    const float4* dp[SS];
#pragma unroll
    for (int s = 0; s < S; ++s)
        dp[s] = (const float4*)(dec + ((b * Nc + s) * Mc + sm) * Vc);

    for (int i = tid; i < NV4; i += THR) {
        float ax = 0.f, ay = 0.f, az = 0.f, aw = 0.f;
#pragma unroll
        for (int s = 0; s < S; ++s) {
            float4 d = dp[s][i];
            ax = fmaf(wl[s], d.x, ax);
            ay = fmaf(wl[s], d.y, ay);
            az = fmaf(wl[s], d.z, az);
            aw = fmaf(wl[s], d.w, aw);
        }
        if (sm == 0 && i == 0) ax += wt0;   // pad one-hot
        float4 r; r.x = ax; r.y = ay; r.z = az; r.w = aw;
        o[i] = r;
    }
}

__global__ __launch_bounds__(THR) void k_fix(
    const float* __restrict__ dec,
    const float* __restrict__ tmpl,
    const int*   __restrict__ spans,
    float*       __restrict__ out)
{
    int b = blockIdx.x >> 6;
    int m = blockIdx.x & 63;
    int tid = threadIdx.x;

    int st = g_srct[b * Mc + m];
    int sm = g_srcm[b * Mc + m];
    if (st == 0 && sm == m) return;     // common case: out_0 already in place

    float4* o = (float4*)(out + (b * Mc + m) * Vc);
    if (st < 0) {
        float4 z; z.x = z.y = z.z = z.w = 0.f;
        for (int i = tid; i < NV4; i += THR) o[i] = z;
        return;
    }
    switch (spans[b]) {
        case 0: row_body<0>(dec, tmpl, b, st, sm, o, tid); break;
        case 1: row_body<1>(dec, tmpl, b, st, sm, o, tid); break;
        case 2: row_body<2>(dec, tmpl, b, st, sm, o, tid); break;
        case 3: row_body<3>(dec, tmpl, b, st, sm, o, tid); break;
        case 4: row_body<4>(dec, tmpl, b, st, sm, o, tid); break;
        default: row_body<5>(dec, tmpl, b, st, sm, o, tid); break;
    }
}

// ---------------------------------------------------------------------------
extern "C" void kernel_launch(void* const* d_in, const int* in_sizes, int n_in,
                              void* d_out, int out_size)
{
    const float* dec   = (const float*)d_in[0];   // [B,N,M,V] fp32
    const float* tmpl  = (const float*)d_in[1];   // [B,T,N+1] fp32
    const int*   spans = (const int*)d_in[2];     // [B] int32
    float*       out   = (float*)d_out;           // [B,M,V] fp32

    k_amax<<<Bc * Mc * CH, THR>>>(dec, tmpl, spans, out);
    k_scan<<<Bc, 32>>>();
    k_fix <<<Bc * Mc, THR>>>(dec, tmpl, spans, out);
}